// round 9
// baseline (speedup 1.0000x reference)
#include <cuda_runtime.h>
#include <math.h>

#define NB 8
#define NS 512
#define NE 64
#define NH 8
#define NW 8
#define SPLITK 4
#define NCHUNK 8
#define ROWS_PB (NS / NCHUNK)       // 64 rows per block
#define KEYS_PT (NS / SPLITK)       // 128 keys per thread

// scratch
__device__ float g_ctx[NB * NS * NE];   // attention context [B,S,E]
__device__ float g_WT[NE * NE];         // WT[e*64+o] = Wo[o*64+e]

typedef unsigned long long u64;

__device__ __forceinline__ u64 pk2(float lo, float hi) {
    u64 r; asm("mov.b64 %0,{%1,%2};" : "=l"(r) : "f"(lo), "f"(hi)); return r;
}
__device__ __forceinline__ void unpk2(u64 v, float& lo, float& hi) {
    asm("mov.b64 {%0,%1},%2;" : "=f"(lo), "=f"(hi) : "l"(v));
}
__device__ __forceinline__ void ffma2(u64& d, u64 a, u64 b) {
    asm("fma.rn.f32x2 %0,%1,%2,%0;" : "+l"(d) : "l"(a), "l"(b));
}
__device__ __forceinline__ void fadd2(u64& d, u64 a) {
    asm("add.rn.f32x2 %0,%0,%1;" : "+l"(d) : "l"(a));
}

// ---------------------------------------------------------------------------
// Kernel 0: transpose Wo once (64x64). One block.
// ---------------------------------------------------------------------------
__global__ void wtrans_kernel(const float* __restrict__ Wo)
{
    const int tid = threadIdx.x;
    for (int i = tid; i < NE * NE; i += 256) {
        const int o = i >> 6, e = i & 63;     // read coalesced
        g_WT[e * NE + o] = Wo[i];
    }
}

// ---------------------------------------------------------------------------
// Kernel 1: analytic quantum heads + self-attention.
//   Block = (b, h, chunk of 64 rows). 4 threads per row, INTERLEAVED key
//   split (t = 4*ti + sub -> conflict-free quad LDS). No softmax max pass
//   (|score| <= sqrt(8)). Packed f32x2 FMA, fast __cosf.
// ---------------------------------------------------------------------------
__global__ __launch_bounds__(256, 4)
void qattn_kernel(const float* __restrict__ x, const float* __restrict__ theta)
{
    __shared__ __align__(16) float q[NS][NW];   // 16 KB

    const int blk   = blockIdx.x;
    const int chunk = blk & (NCHUNK - 1);
    const int h     = (blk >> 3) & (NH - 1);
    const int b     = blk >> 6;
    const int tid   = threadIdx.x;

    float th[NW];
#pragma unroll
    for (int k = 0; k < NW; k++) th[k] = __ldg(&theta[k]);

    // ---- build q for ALL 512 tokens of this head (2 per thread) ----
    // e[j>=1] = prod_{k<=j} cos(x_k+th_k);  e[0] = prod_{k=1..7} cos(x_k+th_k)
    for (int s = tid; s < NS; s += 256) {
        const float* xp = x + ((b * NS + s) * NE + h * NW);
        const float4 xa = *(const float4*)&xp[0];
        const float4 xb = *(const float4*)&xp[4];
        float c[NW];
        c[0] = __cosf(xa.x + th[0]); c[1] = __cosf(xa.y + th[1]);
        c[2] = __cosf(xa.z + th[2]); c[3] = __cosf(xa.w + th[3]);
        c[4] = __cosf(xb.x + th[4]); c[5] = __cosf(xb.y + th[5]);
        c[6] = __cosf(xb.z + th[6]); c[7] = __cosf(xb.w + th[7]);
        float e[NW];
        float run = c[0];
#pragma unroll
        for (int j = 1; j < NW; j++) { run *= c[j]; e[j] = run; }
        float r = c[NW - 1];
#pragma unroll
        for (int j = NW - 2; j >= 1; j--) r *= c[j];
        e[0] = r;
        *(float4*)&q[s][0] = make_float4(e[0], e[1], e[2], e[3]);
        *(float4*)&q[s][4] = make_float4(e[4], e[5], e[6], e[7]);
    }
    __syncthreads();

    const int sub = tid & (SPLITK - 1);            // key-split lane
    const int s   = chunk * ROWS_PB + (tid >> 2);  // query row
    const float scale = 0.35355339059327373f;      // 1/sqrt(8)

    u64 qp[4];
    {
        float4 lo4 = *(const float4*)&q[s][0];
        float4 hi4 = *(const float4*)&q[s][4];
        qp[0] = pk2(lo4.x * scale, lo4.y * scale);
        qp[1] = pk2(lo4.z * scale, lo4.w * scale);
        qp[2] = pk2(hi4.x * scale, hi4.y * scale);
        qp[3] = pk2(hi4.z * scale, hi4.w * scale);
    }

    u64 a2[4] = {0ull, 0ull, 0ull, 0ull};
    float l = 0.f;

#pragma unroll 4
    for (int ti = 0; ti < KEYS_PT; ti++) {
        const int t = (ti << 2) + sub;             // interleaved: quad reads 128B
        ulonglong2 kA = *(const ulonglong2*)&q[t][0];
        ulonglong2 kB = *(const ulonglong2*)&q[t][4];

        u64 d2 = 0ull, d2b = 0ull;
        ffma2(d2,  qp[0], kA.x);
        ffma2(d2b, qp[1], kA.y);
        ffma2(d2,  qp[2], kB.x);
        ffma2(d2b, qp[3], kB.y);
        fadd2(d2, d2b);
        float dl, dh; unpk2(d2, dl, dh);

        const float e = __expf(dl + dh);           // safe: |score| <= 2.83
        l += e;
        const u64 ep = pk2(e, e);
        ffma2(a2[0], ep, kA.x);
        ffma2(a2[1], ep, kA.y);
        ffma2(a2[2], ep, kB.x);
        ffma2(a2[3], ep, kB.y);
    }

    // combine 4 split-K partials (sub lanes adjacent in warp)
#pragma unroll
    for (int o = 1; o <= 2; o <<= 1) {
        l += __shfl_xor_sync(0xffffffffu, l, o);
#pragma unroll
        for (int i = 0; i < 4; i++) {
            u64 other = __shfl_xor_sync(0xffffffffu, a2[i], o);
            fadd2(a2[i], other);
        }
    }

    if (sub == 0) {
        const float inv = 1.f / l;
        float o[NW];
#pragma unroll
        for (int i = 0; i < 4; i++) {
            float lo, hi; unpk2(a2[i], lo, hi);
            o[2 * i] = lo * inv; o[2 * i + 1] = hi * inv;
        }
        float* op = g_ctx + ((b * NS + s) * NE + h * NW);
        *(float4*)&op[0] = make_float4(o[0], o[1], o[2], o[3]);
        *(float4*)&op[4] = make_float4(o[4], o[5], o[6], o[7]);
    }
}

// ---------------------------------------------------------------------------
// Kernel 2: out[r][o] = sum_e ctx[r][e] * WT[e][o] + bo[o]   (4096 x 64 x 64)
// Thread = one output element, o = lane -> every WT load is ONE L1 line per
// warp. grid = 1024 blocks x 4 rows, high occupancy.
// ---------------------------------------------------------------------------
__global__ __launch_bounds__(256, 8)
void proj_kernel(const float* __restrict__ bo, float* __restrict__ out)
{
    __shared__ float R[4][NE];

    const int tid = threadIdx.x;
    const int rowbase = blockIdx.x * 4;

    R[tid >> 6][tid & 63] = g_ctx[rowbase * NE + tid];   // coalesced, 1 KB
    __syncthreads();

    const int r = tid >> 6, o = tid & 63;

    float a0 = __ldg(&bo[o]);
    float a1 = 0.f, a2 = 0.f, a3 = 0.f;
#pragma unroll
    for (int e = 0; e < NE; e += 4) {
        const float4 c = *(const float4*)&R[r][e];      // broadcast LDS
        const float w0 = g_WT[(e + 0) * NE + o];        // coalesced, L1/L2-hot
        const float w1 = g_WT[(e + 1) * NE + o];
        const float w2 = g_WT[(e + 2) * NE + o];
        const float w3 = g_WT[(e + 3) * NE + o];
        a0 = fmaf(c.x, w0, a0);
        a1 = fmaf(c.y, w1, a1);
        a2 = fmaf(c.z, w2, a2);
        a3 = fmaf(c.w, w3, a3);
    }
    out[(rowbase + r) * NE + o] = (a0 + a1) + (a2 + a3);
}

extern "C" void kernel_launch(void* const* d_in, const int* in_sizes, int n_in,
                              void* d_out, int out_size)
{
    const float* x     = (const float*)d_in[0];
    const float* theta = (const float*)d_in[1];
    const float* Wo    = (const float*)d_in[2];
    const float* bo    = (const float*)d_in[3];
    float* out = (float*)d_out;

    wtrans_kernel<<<1, 256>>>(Wo);
    qattn_kernel<<<NB * NH * NCHUNK, 256>>>(x, theta);
    proj_kernel<<<NB * NS / 4, 256>>>(bo, out);
}

// round 11
// speedup vs baseline: 1.1383x; 1.1383x over previous
#include <cuda_runtime.h>
#include <math.h>

#define NB 8
#define NS 512
#define NE 64
#define NH 8
#define NW 8
#define SPLITK 4
#define NCHUNK 8
#define ROWS_PB (NS / NCHUNK)       // 64 rows per block
#define KEYS_PT (NS / SPLITK)       // 128 keys per thread
#define QBLOCKS (NB * NH * NCHUNK)  // 512 attention blocks
#define TBLOCKS 16                  // transpose rider blocks

// scratch
__device__ float g_ctx[NB * NS * NE];   // attention context [B,S,E]
__device__ float g_WT[NE * NE];         // WT[e*64+o] = Wo[o*64+e]

typedef unsigned long long u64;

__device__ __forceinline__ u64 pk2(float lo, float hi) {
    u64 r; asm("mov.b64 %0,{%1,%2};" : "=l"(r) : "f"(lo), "f"(hi)); return r;
}
__device__ __forceinline__ void unpk2(u64 v, float& lo, float& hi) {
    asm("mov.b64 {%0,%1},%2;" : "=f"(lo), "=f"(hi) : "l"(v));
}
__device__ __forceinline__ void ffma2(u64& d, u64 a, u64 b) {
    asm("fma.rn.f32x2 %0,%1,%2,%0;" : "+l"(d) : "l"(a), "l"(b));
}
__device__ __forceinline__ void fadd2(u64& d, u64 a) {
    asm("add.rn.f32x2 %0,%0,%1;" : "+l"(d) : "l"(a));
}

// ---------------------------------------------------------------------------
// Kernel 1: analytic quantum heads + self-attention.
//   Blocks [0, 512): (b, h, chunk of 64 rows). 4 threads per row, interleaved
//   key split (t = 4*ti + sub -> conflict-free quad LDS). No softmax max pass
//   (|score| <= sqrt(8)). Packed f32x2 FMA, fast __cosf.
//   Blocks [512, 528): transpose Wo -> g_WT (hidden under attention work; the
//   stream-order guarantee makes WT visible to proj_kernel).
// ---------------------------------------------------------------------------
__global__ __launch_bounds__(256, 4)
void qattn_kernel(const float* __restrict__ x, const float* __restrict__ theta,
                  const float* __restrict__ Wo)
{
    const int blk = blockIdx.x;
    const int tid = threadIdx.x;

    if (blk >= QBLOCKS) {
        // transpose rider: 16 blocks x 256 threads = 1 element each
        const int i = (blk - QBLOCKS) * 256 + tid;
        const int o = i >> 6, e = i & 63;              // read coalesced
        g_WT[e * NE + o] = Wo[i];
        return;
    }

    __shared__ __align__(16) float q[NS][NW];   // 16 KB

    const int chunk = blk & (NCHUNK - 1);
    const int h     = (blk >> 3) & (NH - 1);
    const int b     = blk >> 6;

    float th[NW];
#pragma unroll
    for (int k = 0; k < NW; k++) th[k] = __ldg(&theta[k]);

    // ---- build q for ALL 512 tokens of this head (2 per thread) ----
    // e[j>=1] = prod_{k<=j} cos(x_k+th_k);  e[0] = prod_{k=1..7} cos(x_k+th_k)
    for (int s = tid; s < NS; s += 256) {
        const float* xp = x + ((b * NS + s) * NE + h * NW);
        const float4 xa = *(const float4*)&xp[0];
        const float4 xb = *(const float4*)&xp[4];
        float c[NW];
        c[0] = __cosf(xa.x + th[0]); c[1] = __cosf(xa.y + th[1]);
        c[2] = __cosf(xa.z + th[2]); c[3] = __cosf(xa.w + th[3]);
        c[4] = __cosf(xb.x + th[4]); c[5] = __cosf(xb.y + th[5]);
        c[6] = __cosf(xb.z + th[6]); c[7] = __cosf(xb.w + th[7]);
        float e[NW];
        float run = c[0];
#pragma unroll
        for (int j = 1; j < NW; j++) { run *= c[j]; e[j] = run; }
        float r = c[NW - 1];
#pragma unroll
        for (int j = NW - 2; j >= 1; j--) r *= c[j];
        e[0] = r;
        *(float4*)&q[s][0] = make_float4(e[0], e[1], e[2], e[3]);
        *(float4*)&q[s][4] = make_float4(e[4], e[5], e[6], e[7]);
    }
    __syncthreads();

    const int sub = tid & (SPLITK - 1);            // key-split lane
    const int s   = chunk * ROWS_PB + (tid >> 2);  // query row
    const float scale = 0.35355339059327373f;      // 1/sqrt(8)

    u64 qp[4];
    {
        float4 lo4 = *(const float4*)&q[s][0];
        float4 hi4 = *(const float4*)&q[s][4];
        qp[0] = pk2(lo4.x * scale, lo4.y * scale);
        qp[1] = pk2(lo4.z * scale, lo4.w * scale);
        qp[2] = pk2(hi4.x * scale, hi4.y * scale);
        qp[3] = pk2(hi4.z * scale, hi4.w * scale);
    }

    u64 a2[4] = {0ull, 0ull, 0ull, 0ull};
    float l = 0.f;

#pragma unroll 4
    for (int ti = 0; ti < KEYS_PT; ti++) {
        const int t = (ti << 2) + sub;             // interleaved: quad reads 128B
        ulonglong2 kA = *(const ulonglong2*)&q[t][0];
        ulonglong2 kB = *(const ulonglong2*)&q[t][4];

        u64 d2 = 0ull, d2b = 0ull;
        ffma2(d2,  qp[0], kA.x);
        ffma2(d2b, qp[1], kA.y);
        ffma2(d2,  qp[2], kB.x);
        ffma2(d2b, qp[3], kB.y);
        fadd2(d2, d2b);
        float dl, dh; unpk2(d2, dl, dh);

        const float e = __expf(dl + dh);           // safe: |score| <= 2.83
        l += e;
        const u64 ep = pk2(e, e);
        ffma2(a2[0], ep, kA.x);
        ffma2(a2[1], ep, kA.y);
        ffma2(a2[2], ep, kB.x);
        ffma2(a2[3], ep, kB.y);
    }

    // combine 4 split-K partials (sub lanes adjacent in warp)
#pragma unroll
    for (int o = 1; o <= 2; o <<= 1) {
        l += __shfl_xor_sync(0xffffffffu, l, o);
#pragma unroll
        for (int i = 0; i < 4; i++) {
            u64 other = __shfl_xor_sync(0xffffffffu, a2[i], o);
            fadd2(a2[i], other);
        }
    }

    if (sub == 0) {
        const float inv = 1.f / l;
        float o[NW];
#pragma unroll
        for (int i = 0; i < 4; i++) {
            float lo, hi; unpk2(a2[i], lo, hi);
            o[2 * i] = lo * inv; o[2 * i + 1] = hi * inv;
        }
        float* op = g_ctx + ((b * NS + s) * NE + h * NW);
        *(float4*)&op[0] = make_float4(o[0], o[1], o[2], o[3]);
        *(float4*)&op[4] = make_float4(o[4], o[5], o[6], o[7]);
    }
}

// ---------------------------------------------------------------------------
// Kernel 2: out[r][o] = sum_e ctx[r][e] * WT[e][o] + bo[o]   (4096 x 64 x 64)
// Thread = 4 outputs of one row via LDG.128 on WT rows (warp reads one 256B
// span, dedup across half-warps). 256 blocks x 16 rows.
// ---------------------------------------------------------------------------
__global__ __launch_bounds__(256, 8)
void proj_kernel(const float* __restrict__ bo, float* __restrict__ out)
{
    __shared__ __align__(16) float R[16][NE];

    const int tid = threadIdx.x;
    const int rowbase = blockIdx.x * 16;

    // 16 ctx rows = 1024 floats, coalesced float4
    {
        const float4 v = ((const float4*)(g_ctx + rowbase * NE))[tid];
        ((float4*)R)[tid] = v;
    }
    __syncthreads();

    const int r  = tid >> 4;            // 16 rows
    const int o0 = (tid & 15) * 4;      // 4 outputs

    float4 acc = *(const float4*)&bo[o0];
    float4 ac2 = make_float4(0.f, 0.f, 0.f, 0.f);
#pragma unroll
    for (int e = 0; e < NE; e += 4) {
        const float4 c = *(const float4*)&R[r][e];           // LDS.128 broadcast
        const float4 w0 = *(const float4*)&g_WT[(e + 0) * NE + o0];
        const float4 w1 = *(const float4*)&g_WT[(e + 1) * NE + o0];
        const float4 w2 = *(const float4*)&g_WT[(e + 2) * NE + o0];
        const float4 w3 = *(const float4*)&g_WT[(e + 3) * NE + o0];
        acc.x = fmaf(c.x, w0.x, acc.x); acc.y = fmaf(c.x, w0.y, acc.y);
        acc.z = fmaf(c.x, w0.z, acc.z); acc.w = fmaf(c.x, w0.w, acc.w);
        ac2.x = fmaf(c.y, w1.x, ac2.x); ac2.y = fmaf(c.y, w1.y, ac2.y);
        ac2.z = fmaf(c.y, w1.z, ac2.z); ac2.w = fmaf(c.y, w1.w, ac2.w);
        acc.x = fmaf(c.z, w2.x, acc.x); acc.y = fmaf(c.z, w2.y, acc.y);
        acc.z = fmaf(c.z, w2.z, acc.z); acc.w = fmaf(c.z, w2.w, acc.w);
        ac2.x = fmaf(c.w, w3.x, ac2.x); ac2.y = fmaf(c.w, w3.y, ac2.y);
        ac2.z = fmaf(c.w, w3.z, ac2.z); ac2.w = fmaf(c.w, w3.w, ac2.w);
    }
    acc.x += ac2.x; acc.y += ac2.y; acc.z += ac2.z; acc.w += ac2.w;
    *(float4*)&out[(rowbase + r) * NE + o0] = acc;
}

extern "C" void kernel_launch(void* const* d_in, const int* in_sizes, int n_in,
                              void* d_out, int out_size)
{
    const float* x     = (const float*)d_in[0];
    const float* theta = (const float*)d_in[1];
    const float* Wo    = (const float*)d_in[2];
    const float* bo    = (const float*)d_in[3];
    float* out = (float*)d_out;

    qattn_kernel<<<QBLOCKS + TBLOCKS, 256>>>(x, theta, Wo);
    proj_kernel<<<NB * NS / 16, 256>>>(bo, out);
}